// round 1
// baseline (speedup 1.0000x reference)
#include <cuda_runtime.h>
#include <math.h>

#define Bn 32
#define Sn 512
#define Dn 512
#define Hn 8
#define DKn 64
#define NEG_INFV -1e30f

// Scratch (allocation-free rule: __device__ globals)
__device__ float g_Q[(size_t)Bn*Hn*Sn*DKn];
__device__ float g_K[(size_t)Bn*Hn*Sn*DKn];
__device__ float g_V[(size_t)Bn*Hn*Sn*DKn];
__device__ float g_O[(size_t)Bn*Sn*Dn];

// ---------------------------------------------------------------------------
// QKV projection: out[b,h,s,k] = sum_d x[b,s,d] * W[h,d,k] + bias
// grid (S/64, H, B), block 256. 64x64 tile, K-chunk 16, 4x4 per thread.
// ---------------------------------------------------------------------------
__global__ void qkv_kernel(const float* __restrict__ x,
                           const float* __restrict__ W,
                           const float* __restrict__ bias,
                           int which)
{
    __shared__ float As[64][17];
    __shared__ float Bs[16][64];

    int b  = blockIdx.z;
    int h  = blockIdx.y;
    int s0 = blockIdx.x * 64;
    int tid = threadIdx.x;
    int tx = tid & 15;
    int ty = tid >> 4;

    const float* xA = x + ((size_t)b * Sn + s0) * Dn;
    const float* Wh = W + (size_t)h * Dn * DKn;

    float c[4][4] = {};

    for (int d0 = 0; d0 < Dn; d0 += 16) {
        // A tile: 64 rows x 16 cols
        {
            int row = tid >> 2;
            int c4  = (tid & 3) * 4;
            float4 v = *(const float4*)(xA + (size_t)row * Dn + d0 + c4);
            As[row][c4+0] = v.x; As[row][c4+1] = v.y;
            As[row][c4+2] = v.z; As[row][c4+3] = v.w;
        }
        // B tile: 16 rows x 64 cols
        {
            int row = tid >> 4;
            int c4  = (tid & 15) * 4;
            *(float4*)&Bs[row][c4] = *(const float4*)(Wh + (size_t)(d0+row) * DKn + c4);
        }
        __syncthreads();

        #pragma unroll
        for (int kk = 0; kk < 16; kk++) {
            float a[4], bb[4];
            #pragma unroll
            for (int i = 0; i < 4; i++) a[i]  = As[ty + i*16][kk];
            #pragma unroll
            for (int j = 0; j < 4; j++) bb[j] = Bs[kk][tx + j*16];
            #pragma unroll
            for (int i = 0; i < 4; i++)
                #pragma unroll
                for (int j = 0; j < 4; j++)
                    c[i][j] += a[i] * bb[j];
        }
        __syncthreads();
    }

    float bv = bias[0];
    float* out = (which == 0) ? g_Q : (which == 1) ? g_K : g_V;
    float* o = out + (((size_t)b * Hn + h) * Sn + s0) * DKn;
    #pragma unroll
    for (int i = 0; i < 4; i++)
        #pragma unroll
        for (int j = 0; j < 4; j++)
            o[(size_t)(ty + i*16) * DKn + tx + j*16] = c[i][j] + bv;
}

// ---------------------------------------------------------------------------
// Attention: per (b,h), flash-style. 1 thread = 1 query row. 128 rows/block.
// grid (S/128, H, B), block 128. K/V tiles of 32 keys in smem.
// Output written as O[b, s, h*64 + d]  (concat-head layout for the out-proj).
// ---------------------------------------------------------------------------
__global__ void __launch_bounds__(128)
attn_kernel(const int* __restrict__ mask)
{
    __shared__ float sm[8192];   // 32 KB: Q staging, then K(2048) | V(2048) | mask

    int b  = blockIdx.z;
    int h  = blockIdx.y;
    int q0 = blockIdx.x * 128;
    int t  = threadIdx.x;

    const float* Qb = g_Q + (((size_t)b * Hn + h) * Sn + q0) * DKn;
    const float* Kb = g_K + ((size_t)b * Hn + h) * Sn * DKn;
    const float* Vb = g_V + ((size_t)b * Hn + h) * Sn * DKn;

    // Stage Q tile (128x64 contiguous) into smem, coalesced; then to registers.
    for (int i = t; i < 2048; i += 128)
        ((float4*)sm)[i] = ((const float4*)Qb)[i];
    __syncthreads();

    float q[64];
    #pragma unroll
    for (int d = 0; d < 64; d += 4) {
        float4 v = *(const float4*)&sm[t*64 + d];
        q[d] = v.x; q[d+1] = v.y; q[d+2] = v.z; q[d+3] = v.w;
    }

    float acc[64] = {};
    float mrow = -INFINITY;
    float l = 0.0f;

    float* Ks = sm;
    float* Vs = sm + 2048;
    int*   mk = (int*)(sm + 4096);

    for (int kt = 0; kt < Sn; kt += 32) {
        __syncthreads();   // acc of previous tile done; safe to overwrite K/V
        for (int i = t; i < 512; i += 128) {
            ((float4*)Ks)[i] = ((const float4*)(Kb + (size_t)kt * 64))[i];
            ((float4*)Vs)[i] = ((const float4*)(Vb + (size_t)kt * 64))[i];
        }
        if (t < 32) mk[t] = mask[(size_t)b * Sn + kt + t];
        __syncthreads();

        // Scores for 32 keys, 4 at a time (independent FMA chains).
        float p[32];
        float tmax = -INFINITY;
        #pragma unroll
        for (int j4 = 0; j4 < 32; j4 += 4) {
            float s0 = 0.f, s1 = 0.f, s2 = 0.f, s3 = 0.f;
            #pragma unroll
            for (int d = 0; d < 64; d += 4) {
                float4 k0 = *(float4*)&Ks[(j4+0)*64 + d];
                float4 k1 = *(float4*)&Ks[(j4+1)*64 + d];
                float4 k2 = *(float4*)&Ks[(j4+2)*64 + d];
                float4 k3 = *(float4*)&Ks[(j4+3)*64 + d];
                s0 += q[d]*k0.x + q[d+1]*k0.y + q[d+2]*k0.z + q[d+3]*k0.w;
                s1 += q[d]*k1.x + q[d+1]*k1.y + q[d+2]*k1.z + q[d+3]*k1.w;
                s2 += q[d]*k2.x + q[d+1]*k2.y + q[d+2]*k2.z + q[d+3]*k2.w;
                s3 += q[d]*k3.x + q[d+1]*k3.y + q[d+2]*k3.z + q[d+3]*k3.w;
            }
            // mask m in {0,1}: m*s*scale + (1-m)*NEG_INF  ==  select
            p[j4+0] = mk[j4+0] ? s0 * 0.125f : NEG_INFV;
            p[j4+1] = mk[j4+1] ? s1 * 0.125f : NEG_INFV;
            p[j4+2] = mk[j4+2] ? s2 * 0.125f : NEG_INFV;
            p[j4+3] = mk[j4+3] ? s3 * 0.125f : NEG_INFV;
            tmax = fmaxf(tmax, fmaxf(fmaxf(p[j4+0], p[j4+1]), fmaxf(p[j4+2], p[j4+3])));
        }

        float newm = fmaxf(mrow, tmax);
        float corr = __expf(mrow - newm);   // first iter: exp(-inf) = 0
        float lsum = 0.f;
        #pragma unroll
        for (int j = 0; j < 32; j++) {
            p[j] = __expf(p[j] - newm);
            lsum += p[j];
        }
        l = l * corr + lsum;
        mrow = newm;
        #pragma unroll
        for (int d = 0; d < 64; d++) acc[d] *= corr;

        #pragma unroll
        for (int j = 0; j < 32; j++) {
            float pj = p[j];
            #pragma unroll
            for (int d = 0; d < 64; d += 4) {
                float4 v = *(float4*)&Vs[j*64 + d];
                acc[d+0] += pj * v.x;
                acc[d+1] += pj * v.y;
                acc[d+2] += pj * v.z;
                acc[d+3] += pj * v.w;
            }
        }
    }

    float inv = 1.0f / l;
    float* o = g_O + ((size_t)b * Sn + (q0 + t)) * Dn + h * DKn;
    #pragma unroll
    for (int d = 0; d < 64; d += 4) {
        float4 v = make_float4(acc[d]*inv, acc[d+1]*inv, acc[d+2]*inv, acc[d+3]*inv);
        *(float4*)(o + d) = v;
    }
}

// ---------------------------------------------------------------------------
// Output projection: out[r,c] = sum_k O[r,k] * Wo[k,c] + bias
// grid (16384/64, 512/64), block 256. Same tiling as qkv_kernel.
// ---------------------------------------------------------------------------
__global__ void proj_kernel(const float* __restrict__ Wo,
                            const float* __restrict__ bias,
                            float* __restrict__ out)
{
    __shared__ float As[64][17];
    __shared__ float Bs[16][64];

    int r0 = blockIdx.x * 64;
    int c0 = blockIdx.y * 64;
    int tid = threadIdx.x;
    int tx = tid & 15;
    int ty = tid >> 4;

    float c[4][4] = {};

    for (int d0 = 0; d0 < Dn; d0 += 16) {
        {
            int row = tid >> 2;
            int c4  = (tid & 3) * 4;
            float4 v = *(const float4*)(g_O + (size_t)(r0+row) * Dn + d0 + c4);
            As[row][c4+0] = v.x; As[row][c4+1] = v.y;
            As[row][c4+2] = v.z; As[row][c4+3] = v.w;
        }
        {
            int row = tid >> 4;
            int c4  = (tid & 15) * 4;
            *(float4*)&Bs[row][c4] = *(const float4*)(Wo + (size_t)(d0+row) * Dn + c0 + c4);
        }
        __syncthreads();

        #pragma unroll
        for (int kk = 0; kk < 16; kk++) {
            float a[4], bb[4];
            #pragma unroll
            for (int i = 0; i < 4; i++) a[i]  = As[ty + i*16][kk];
            #pragma unroll
            for (int j = 0; j < 4; j++) bb[j] = Bs[kk][tx + j*16];
            #pragma unroll
            for (int i = 0; i < 4; i++)
                #pragma unroll
                for (int j = 0; j < 4; j++)
                    c[i][j] += a[i] * bb[j];
        }
        __syncthreads();
    }

    float bv = bias[0];
    #pragma unroll
    for (int i = 0; i < 4; i++)
        #pragma unroll
        for (int j = 0; j < 4; j++)
            out[(size_t)(r0 + ty + i*16) * Dn + c0 + tx + j*16] = c[i][j] + bv;
}

// ---------------------------------------------------------------------------
extern "C" void kernel_launch(void* const* d_in, const int* in_sizes, int n_in,
                              void* d_out, int out_size)
{
    const float* x    = (const float*)d_in[0];
    const int*   mask = (const int*)  d_in[1];
    const float* Wq   = (const float*)d_in[2];
    const float* Wk   = (const float*)d_in[3];
    const float* Wv   = (const float*)d_in[4];
    const float* Wo   = (const float*)d_in[5];
    const float* bias = (const float*)d_in[6];
    float* out = (float*)d_out;

    dim3 gq(Sn / 64, Hn, Bn);
    qkv_kernel<<<gq, 256>>>(x, Wq, bias, 0);
    qkv_kernel<<<gq, 256>>>(x, Wk, bias, 1);
    qkv_kernel<<<gq, 256>>>(x, Wv, bias, 2);

    dim3 ga(Sn / 128, Hn, Bn);
    attn_kernel<<<ga, 128>>>(mask);

    dim3 gp((Bn * Sn) / 64, Dn / 64);
    proj_kernel<<<gp, 256>>>(Wo, bias, out);
}

// round 3
// speedup vs baseline: 1.7495x; 1.7495x over previous
#include <cuda_runtime.h>
#include <cuda_bf16.h>
#include <math.h>
#include <stdint.h>

#define Bn 32
#define Sn 512
#define Dn 512
#define Hn 8
#define DKn 64
#define NEG_INFV -1e30f

// ---------------------------------------------------------------------------
// Scratch (__device__ globals; no allocation allowed)
// ---------------------------------------------------------------------------
__device__ float g_Q[(size_t)Bn*Hn*Sn*DKn];
__device__ float g_K[(size_t)Bn*Hn*Sn*DKn];
__device__ float g_V[(size_t)Bn*Hn*Sn*DKn];
__device__ float g_O[(size_t)Bn*Sn*Dn];

__device__ __align__(16) __nv_bfloat16 gXh[(size_t)Bn*Sn*Dn];
__device__ __align__(16) __nv_bfloat16 gXl[(size_t)Bn*Sn*Dn];
__device__ __align__(16) __nv_bfloat16 gOh[(size_t)Bn*Sn*Dn];
__device__ __align__(16) __nv_bfloat16 gOl[(size_t)Bn*Sn*Dn];
__device__ __align__(16) __nv_bfloat16 gWh[3][(size_t)Hn*DKn*Dn];
__device__ __align__(16) __nv_bfloat16 gWl[3][(size_t)Hn*DKn*Dn];
__device__ __align__(16) __nv_bfloat16 gWoh[(size_t)Dn*Dn];
__device__ __align__(16) __nv_bfloat16 gWol[(size_t)Dn*Dn];

// ---------------------------------------------------------------------------
// mma.sync / ldmatrix helpers (generic PTX, works on non-'a' targets)
// ---------------------------------------------------------------------------
__device__ __forceinline__ uint32_t smem_u32(const void* p) {
    uint32_t a;
    asm("{ .reg .u64 t; cvta.to.shared.u64 t, %1; cvt.u32.u64 %0, t; }" : "=r"(a) : "l"(p));
    return a;
}

__device__ __forceinline__ void ldsm_x4(uint32_t* r, uint32_t addr) {
    asm volatile("ldmatrix.sync.aligned.m8n8.x4.shared.b16 {%0,%1,%2,%3}, [%4];"
        : "=r"(r[0]), "=r"(r[1]), "=r"(r[2]), "=r"(r[3]) : "r"(addr));
}

__device__ __forceinline__ void mma16816(float* d, const uint32_t* a, const uint32_t* b) {
    asm volatile("mma.sync.aligned.m16n8k16.row.col.f32.bf16.bf16.f32 "
        "{%0,%1,%2,%3}, {%4,%5,%6,%7}, {%8,%9}, {%0,%1,%2,%3};"
        : "+f"(d[0]), "+f"(d[1]), "+f"(d[2]), "+f"(d[3])
        : "r"(a[0]), "r"(a[1]), "r"(a[2]), "r"(a[3]), "r"(b[0]), "r"(b[1]));
}

// ---------------------------------------------------------------------------
// fp32 -> bf16 hi/lo split. dst=0: x -> gXh/gXl ; dst=1: g_O -> gOh/gOl
// ---------------------------------------------------------------------------
__global__ void cvt_kernel(const float* __restrict__ xin, int dst)
{
    size_t i = ((size_t)blockIdx.x * blockDim.x + threadIdx.x) * 4;
    const float* in = (dst == 0) ? xin : g_O;
    __nv_bfloat16* hi = (dst == 0) ? gXh : gOh;
    __nv_bfloat16* lo = (dst == 0) ? gXl : gOl;
    float4 v = *(const float4*)(in + i);
    __nv_bfloat16 h0 = __float2bfloat16(v.x), h1 = __float2bfloat16(v.y);
    __nv_bfloat16 h2 = __float2bfloat16(v.z), h3 = __float2bfloat16(v.w);
    __nv_bfloat16 l0 = __float2bfloat16(v.x - __bfloat162float(h0));
    __nv_bfloat16 l1 = __float2bfloat16(v.y - __bfloat162float(h1));
    __nv_bfloat16 l2 = __float2bfloat16(v.z - __bfloat162float(h2));
    __nv_bfloat16 l3 = __float2bfloat16(v.w - __bfloat162float(h3));
    __nv_bfloat162* hp = (__nv_bfloat162*)(hi + i);
    __nv_bfloat162* lp = (__nv_bfloat162*)(lo + i);
    hp[0] = __nv_bfloat162(h0, h1); hp[1] = __nv_bfloat162(h2, h3);
    lp[0] = __nv_bfloat162(l0, l1); lp[1] = __nv_bfloat162(l2, l3);
}

// W [H, D, DK] -> gW*[which] as [H, DK(n), D(k)] K-major, split hi/lo
__global__ void wprep_kernel(const float* __restrict__ W, int which)
{
    int h = blockIdx.z;
    int idx = blockIdx.x * 256 + threadIdx.x;
    int n = idx >> 9, k = idx & 511;
    float a = W[(size_t)h * Dn * DKn + (size_t)k * DKn + n];
    __nv_bfloat16 hh = __float2bfloat16(a);
    __nv_bfloat16 ll = __float2bfloat16(a - __bfloat162float(hh));
    size_t o = (size_t)h * DKn * Dn + (size_t)n * Dn + k;
    gWh[which][o] = hh;
    gWl[which][o] = ll;
}

// Wo [D, D] -> gWo* as [D(n), D(k)] K-major, split hi/lo
__global__ void woprep_kernel(const float* __restrict__ Wo)
{
    int idx = blockIdx.x * 256 + threadIdx.x;
    int n = idx >> 9, k = idx & 511;
    float a = Wo[(size_t)k * Dn + n];
    __nv_bfloat16 hh = __float2bfloat16(a);
    __nv_bfloat16 ll = __float2bfloat16(a - __bfloat162float(hh));
    gWoh[(size_t)n * Dn + k] = hh;
    gWol[(size_t)n * Dn + k] = ll;
}

// ---------------------------------------------------------------------------
// mma.sync split-bf16 GEMM: C[128 x 64] = A[128 x 512] * B[64 x 512]^T + bias
// mode 0/1/2: QKV (A = gX*, B = gW*[mode], C = g_Q/g_K/g_V)
// mode 3:     out-proj (A = gO*, B = gWo*, C = Cout)
// 256 threads, 8 warps in 4x2; warp tile 32x32; K chunk = 64.
// smem tiles padded to 72 bf16 (144 B) per row: ldmatrix phases conflict-free.
// ---------------------------------------------------------------------------
#define PAD 72
#define AS_H 0
#define AS_L (128 * 144)
#define BS_H (2 * 128 * 144)
#define BS_L (2 * 128 * 144 + 64 * 144)
#define SM_BYTES (2 * 128 * 144 + 2 * 64 * 144)   // 55296

__global__ void __launch_bounds__(256)
gemm_tc_kernel(float* __restrict__ Cout, const float* __restrict__ bias, int mode)
{
    extern __shared__ __align__(16) char smem[];
    uint32_t sb = smem_u32(smem);
    int tid  = threadIdx.x;
    int lane = tid & 31;
    int wid  = tid >> 5;
    int wm   = wid & 3;        // 0..3 (M direction, 32 rows each)
    int wn   = wid >> 2;       // 0..1 (N direction, 32 cols each)

    const __nv_bfloat16 *Ah, *Al, *Bh, *Bl;
    float* C;
    size_t arow, bb, cb;
    int ldc;
    if (mode < 3) {
        Ah = gXh; Al = gXl;
        Bh = gWh[mode]; Bl = gWl[mode];
        C = (mode == 0) ? g_Q : (mode == 1) ? g_K : g_V;
        arow = (size_t)blockIdx.z * Sn + blockIdx.x * 128;
        bb   = (size_t)blockIdx.y * DKn * Dn;
        cb   = (((size_t)blockIdx.z * Hn + blockIdx.y) * Sn + blockIdx.x * 128) * DKn;
        ldc  = DKn;
    } else {
        Ah = gOh; Al = gOl;
        Bh = gWoh; Bl = gWol;
        C = Cout;
        arow = (size_t)blockIdx.x * 128;
        bb   = (size_t)blockIdx.y * 64 * Dn;
        cb   = (size_t)blockIdx.x * 128 * Dn + blockIdx.y * 64;
        ldc  = Dn;
    }

    float acc[2][4][4] = {};

    // ldmatrix per-thread base offsets (bytes into each tile)
    // A (m16k16, x4): lane -> row (lane%16), k-half (lane/16)
    uint32_t aoff = (uint32_t)((wm * 32 + (lane & 15)) * 144 + (lane >> 4) * 16);
    // B (n16k16, x4): lane -> n row, k-half
    uint32_t boff = (uint32_t)((wn * 32 + (lane & 7) + ((lane >> 4) << 3)) * 144 +
                               (((lane >> 3) & 1) << 4));

    int ldr = tid >> 3;        // 0..31
    int ldcnk = tid & 7;       // 16B chunk 0..7 within 128B row

    for (int ck = 0; ck < 8; ck++) {
        int kof = ck * 64;

        // fill A tiles (128 rows x 64 bf16, hi & lo)
        #pragma unroll
        for (int p = 0; p < 4; p++) {
            int r = p * 32 + ldr;
            const uint4* ph = (const uint4*)(Ah + (arow + r) * (size_t)Dn + kof + ldcnk * 8);
            const uint4* pl = (const uint4*)(Al + (arow + r) * (size_t)Dn + kof + ldcnk * 8);
            *(uint4*)(smem + AS_H + r * 144 + ldcnk * 16) = *ph;
            *(uint4*)(smem + AS_L + r * 144 + ldcnk * 16) = *pl;
        }
        // fill B tiles (64 rows x 64 bf16, hi & lo)
        #pragma unroll
        for (int p = 0; p < 2; p++) {
            int r = p * 32 + ldr;
            const uint4* ph = (const uint4*)(Bh + bb + r * (size_t)Dn + kof + ldcnk * 8);
            const uint4* pl = (const uint4*)(Bl + bb + r * (size_t)Dn + kof + ldcnk * 8);
            *(uint4*)(smem + BS_H + r * 144 + ldcnk * 16) = *ph;
            *(uint4*)(smem + BS_L + r * 144 + ldcnk * 16) = *pl;
        }
        __syncthreads();

        #pragma unroll
        for (int kk = 0; kk < 4; kk++) {
            uint32_t ah[2][4], al[2][4], bh[4][2], bl[4][2];
            #pragma unroll
            for (int mf = 0; mf < 2; mf++) {
                ldsm_x4(ah[mf], sb + AS_H + aoff + mf * (16 * 144) + kk * 32);
                ldsm_x4(al[mf], sb + AS_L + aoff + mf * (16 * 144) + kk * 32);
            }
            #pragma unroll
            for (int f2 = 0; f2 < 2; f2++) {
                uint32_t t4[4];
                ldsm_x4(t4, sb + BS_H + boff + f2 * (16 * 144) + kk * 32);
                bh[f2*2+0][0] = t4[0]; bh[f2*2+0][1] = t4[1];
                bh[f2*2+1][0] = t4[2]; bh[f2*2+1][1] = t4[3];
                ldsm_x4(t4, sb + BS_L + boff + f2 * (16 * 144) + kk * 32);
                bl[f2*2+0][0] = t4[0]; bl[f2*2+0][1] = t4[1];
                bl[f2*2+1][0] = t4[2]; bl[f2*2+1][1] = t4[3];
            }
            #pragma unroll
            for (int mf = 0; mf < 2; mf++)
                #pragma unroll
                for (int nf = 0; nf < 4; nf++) {
                    mma16816(acc[mf][nf], ah[mf], bh[nf]);   // hi*hi
                    mma16816(acc[mf][nf], ah[mf], bl[nf]);   // hi*lo
                    mma16816(acc[mf][nf], al[mf], bh[nf]);   // lo*hi
                }
        }
        __syncthreads();
    }

    // Epilogue: c fragment (m16n8): d0,d1 @ (row, 2c), d2,d3 @ (row+8, 2c)
    float bv = bias[0];
    int rbase = wm * 32 + (lane >> 2);
    int cbase = wn * 32 + (lane & 3) * 2;
    #pragma unroll
    for (int mf = 0; mf < 2; mf++)
        #pragma unroll
        for (int nf = 0; nf < 4; nf++) {
            int r = rbase + mf * 16;
            int c = cbase + nf * 8;
            float2 v0 = make_float2(acc[mf][nf][0] + bv, acc[mf][nf][1] + bv);
            float2 v1 = make_float2(acc[mf][nf][2] + bv, acc[mf][nf][3] + bv);
            *(float2*)(C + cb + (size_t)r * ldc + c)       = v0;
            *(float2*)(C + cb + (size_t)(r + 8) * ldc + c) = v1;
        }
}

// ---------------------------------------------------------------------------
// Attention (unchanged): flash-style, 1 thread / query row.
// ---------------------------------------------------------------------------
__global__ void __launch_bounds__(128)
attn_kernel(const int* __restrict__ mask)
{
    __shared__ float sm[8192];

    int b  = blockIdx.z;
    int h  = blockIdx.y;
    int q0 = blockIdx.x * 128;
    int t  = threadIdx.x;

    const float* Qb = g_Q + (((size_t)b * Hn + h) * Sn + q0) * DKn;
    const float* Kb = g_K + ((size_t)b * Hn + h) * Sn * DKn;
    const float* Vb = g_V + ((size_t)b * Hn + h) * Sn * DKn;

    for (int i = t; i < 2048; i += 128)
        ((float4*)sm)[i] = ((const float4*)Qb)[i];
    __syncthreads();

    float q[64];
    #pragma unroll
    for (int d = 0; d < 64; d += 4) {
        float4 v = *(const float4*)&sm[t*64 + d];
        q[d] = v.x; q[d+1] = v.y; q[d+2] = v.z; q[d+3] = v.w;
    }

    float acc[64] = {};
    float mrow = -INFINITY;
    float l = 0.0f;

    float* Ks = sm;
    float* Vs = sm + 2048;
    int*   mk = (int*)(sm + 4096);

    for (int kt = 0; kt < Sn; kt += 32) {
        __syncthreads();
        for (int i = t; i < 512; i += 128) {
            ((float4*)Ks)[i] = ((const float4*)(Kb + (size_t)kt * 64))[i];
            ((float4*)Vs)[i] = ((const float4*)(Vb + (size_t)kt * 64))[i];
        }
        if (t < 32) mk[t] = mask[(size_t)b * Sn + kt + t];
        __syncthreads();

        float p[32];
        float tmax = -INFINITY;
        #pragma unroll
        for (int j4 = 0; j4 < 32; j4 += 4) {
            float s0 = 0.f, s1 = 0.f, s2 = 0.f, s3 = 0.f;
            #pragma unroll
            for (int d = 0; d < 64; d += 4) {
                float4 k0 = *(float4*)&Ks[(j4+0)*64 + d];
                float4 k1 = *(float4*)&Ks[(j4+1)*64 + d];
                float4 k2 = *(float4*)&Ks[(j4+2)*64 + d];
                float4 k3 = *(float4*)&Ks[(j4+3)*64 + d];
                s0 += q[d]*k0.x + q[d+1]*k0.y + q[d+2]*k0.z + q[d+3]*k0.w;
                s1 += q[d]*k1.x + q[d+1]*k1.y + q[d+2]*k1.z + q[d+3]*k1.w;
                s2 += q[d]*k2.x + q[d+1]*k2.y + q[d+2]*k2.z + q[d+3]*k2.w;
                s3 += q[d]*k3.x + q[d+1]*k3.y + q[d+2]*k3.z + q[d+3]*k3.w;
            }
            p[j4+0] = mk[j4+0] ? s0 * 0.125f : NEG_INFV;
            p[j4+1] = mk[j4+1] ? s1 * 0.125f : NEG_INFV;
            p[j4+2] = mk[j4+2] ? s2 * 0.125f : NEG_INFV;
            p[j4+3] = mk[j4+3] ? s3 * 0.125f : NEG_INFV;
            tmax = fmaxf(tmax, fmaxf(fmaxf(p[j4+0], p[j4+1]), fmaxf(p[j4+2], p[j4+3])));
        }

        float newm = fmaxf(mrow, tmax);
        float corr = __expf(mrow - newm);
        float lsum = 0.f;
        #pragma unroll
        for (int j = 0; j < 32; j++) {
            p[j] = __expf(p[j] - newm);
            lsum += p[j];
        }
        l = l * corr + lsum;
        mrow = newm;
        #pragma unroll
        for (int d = 0; d < 64; d++) acc[d] *= corr;

        #pragma unroll
        for (int j = 0; j < 32; j++) {
            float pj = p[j];
            #pragma unroll
            for (int d = 0; d < 64; d += 4) {
                float4 v = *(float4*)&Vs[j*64 + d];
                acc[d+0] += pj * v.x;
                acc[d+1] += pj * v.y;
                acc[d+2] += pj * v.z;
                acc[d+3] += pj * v.w;
            }
        }
    }

    float inv = 1.0f / l;
    float* o = g_O + ((size_t)b * Sn + (q0 + t)) * Dn + h * DKn;
    #pragma unroll
    for (int d = 0; d < 64; d += 4) {
        float4 v = make_float4(acc[d]*inv, acc[d+1]*inv, acc[d+2]*inv, acc[d+3]*inv);
        *(float4*)(o + d) = v;
    }
}

// ---------------------------------------------------------------------------
extern "C" void kernel_launch(void* const* d_in, const int* in_sizes, int n_in,
                              void* d_out, int out_size)
{
    const float* x    = (const float*)d_in[0];
    const int*   mask = (const int*)  d_in[1];
    const float* Wq   = (const float*)d_in[2];
    const float* Wk   = (const float*)d_in[3];
    const float* Wv   = (const float*)d_in[4];
    const float* Wo   = (const float*)d_in[5];
    const float* bias = (const float*)d_in[6];
    float* out = (float*)d_out;

    cudaFuncSetAttribute(gemm_tc_kernel,
                         cudaFuncAttributeMaxDynamicSharedMemorySize, SM_BYTES);

    // Prep: split x and weights into bf16 hi/lo (weights transposed to K-major)
    cvt_kernel<<<(Bn * Sn * Dn) / (4 * 256), 256>>>(x, 0);
    dim3 gw(128, 1, Hn);
    wprep_kernel<<<gw, 256>>>(Wq, 0);
    wprep_kernel<<<gw, 256>>>(Wk, 1);
    wprep_kernel<<<gw, 256>>>(Wv, 2);
    woprep_kernel<<<1024, 256>>>(Wo);

    // QKV projections on tensor cores (mma.sync)
    dim3 gq(Sn / 128, Hn, Bn);
    gemm_tc_kernel<<<gq, 256, SM_BYTES>>>(nullptr, bias, 0);
    gemm_tc_kernel<<<gq, 256, SM_BYTES>>>(nullptr, bias, 1);
    gemm_tc_kernel<<<gq, 256, SM_BYTES>>>(nullptr, bias, 2);

    // Attention (fp32)
    dim3 ga(Sn / 128, Hn, Bn);
    attn_kernel<<<ga, 128>>>(mask);

    // Output projection on tensor cores
    cvt_kernel<<<(Bn * Sn * Dn) / (4 * 256), 256>>>(x, 1);
    dim3 gp((Bn * Sn) / 128, Dn / 64, 1);
    gemm_tc_kernel<<<gp, 256, SM_BYTES>>>(out, bias, 3);
}

// round 4
// speedup vs baseline: 3.8474x; 2.1991x over previous
#include <cuda_runtime.h>
#include <cuda_bf16.h>
#include <math.h>
#include <stdint.h>

#define Bn 32
#define Sn 512
#define Dn 512
#define Hn 8
#define DKn 64
#define NEG_INFV -1e30f
#define SCALE 0.125f

// ---------------------------------------------------------------------------
// Scratch (__device__ globals)
// ---------------------------------------------------------------------------
__device__ __align__(16) __nv_bfloat16 gXh[(size_t)Bn*Sn*Dn];
__device__ __align__(16) __nv_bfloat16 gXl[(size_t)Bn*Sn*Dn];
__device__ __align__(16) __nv_bfloat16 gOh[(size_t)Bn*Sn*Dn];
__device__ __align__(16) __nv_bfloat16 gOl[(size_t)Bn*Sn*Dn];
__device__ __align__(16) __nv_bfloat16 gWh[3][(size_t)Hn*DKn*Dn];
__device__ __align__(16) __nv_bfloat16 gWl[3][(size_t)Hn*DKn*Dn];
__device__ __align__(16) __nv_bfloat16 gWoh[(size_t)Dn*Dn];
__device__ __align__(16) __nv_bfloat16 gWol[(size_t)Dn*Dn];
// attention operands (bf16 split), Q/K: [B,H,S,DK], Vt: [B,H,DK,S]
__device__ __align__(16) __nv_bfloat16 gQh[(size_t)Bn*Hn*Sn*DKn];
__device__ __align__(16) __nv_bfloat16 gQl[(size_t)Bn*Hn*Sn*DKn];
__device__ __align__(16) __nv_bfloat16 gKh[(size_t)Bn*Hn*Sn*DKn];
__device__ __align__(16) __nv_bfloat16 gKl[(size_t)Bn*Hn*Sn*DKn];
__device__ __align__(16) __nv_bfloat16 gVth[(size_t)Bn*Hn*DKn*Sn];
__device__ __align__(16) __nv_bfloat16 gVtl[(size_t)Bn*Hn*DKn*Sn];

// ---------------------------------------------------------------------------
// mma.sync / ldmatrix helpers
// ---------------------------------------------------------------------------
__device__ __forceinline__ uint32_t smem_u32(const void* p) {
    uint32_t a;
    asm("{ .reg .u64 t; cvta.to.shared.u64 t, %1; cvt.u32.u64 %0, t; }" : "=r"(a) : "l"(p));
    return a;
}

__device__ __forceinline__ void ldsm_x4(uint32_t* r, uint32_t addr) {
    asm volatile("ldmatrix.sync.aligned.m8n8.x4.shared.b16 {%0,%1,%2,%3}, [%4];"
        : "=r"(r[0]), "=r"(r[1]), "=r"(r[2]), "=r"(r[3]) : "r"(addr));
}

__device__ __forceinline__ void mma16816(float* d, const uint32_t* a, const uint32_t* b) {
    asm volatile("mma.sync.aligned.m16n8k16.row.col.f32.bf16.bf16.f32 "
        "{%0,%1,%2,%3}, {%4,%5,%6,%7}, {%8,%9}, {%0,%1,%2,%3};"
        : "+f"(d[0]), "+f"(d[1]), "+f"(d[2]), "+f"(d[3])
        : "r"(a[0]), "r"(a[1]), "r"(a[2]), "r"(a[3]), "r"(b[0]), "r"(b[1]));
}

__device__ __forceinline__ void split2(float a, float b, uint32_t& hi, uint32_t& lo) {
    __nv_bfloat16 ha = __float2bfloat16(a), hb = __float2bfloat16(b);
    __nv_bfloat16 la = __float2bfloat16(a - __bfloat162float(ha));
    __nv_bfloat16 lb = __float2bfloat16(b - __bfloat162float(hb));
    __nv_bfloat162 H(ha, hb), L(la, lb);
    hi = *(uint32_t*)&H; lo = *(uint32_t*)&L;
}

// ---------------------------------------------------------------------------
// Prep kernels
// ---------------------------------------------------------------------------
__global__ void cvt_kernel(const float* __restrict__ xin)
{
    size_t i = ((size_t)blockIdx.x * blockDim.x + threadIdx.x) * 4;
    float4 v = *(const float4*)(xin + i);
    uint32_t h0, l0, h1, l1;
    split2(v.x, v.y, h0, l0);
    split2(v.z, v.w, h1, l1);
    uint32_t* hp = (uint32_t*)(gXh + i);
    uint32_t* lp = (uint32_t*)(gXl + i);
    hp[0] = h0; hp[1] = h1;
    lp[0] = l0; lp[1] = l1;
}

__global__ void wprep_kernel(const float* __restrict__ W, int which)
{
    int h = blockIdx.z;
    int idx = blockIdx.x * 256 + threadIdx.x;
    int n = idx >> 9, k = idx & 511;
    float a = W[(size_t)h * Dn * DKn + (size_t)k * DKn + n];
    __nv_bfloat16 hh = __float2bfloat16(a);
    __nv_bfloat16 ll = __float2bfloat16(a - __bfloat162float(hh));
    size_t o = (size_t)h * DKn * Dn + (size_t)n * Dn + k;
    gWh[which][o] = hh;
    gWl[which][o] = ll;
}

__global__ void woprep_kernel(const float* __restrict__ Wo)
{
    int idx = blockIdx.x * 256 + threadIdx.x;
    int n = idx >> 9, k = idx & 511;
    float a = Wo[(size_t)k * Dn + n];
    __nv_bfloat16 hh = __float2bfloat16(a);
    __nv_bfloat16 ll = __float2bfloat16(a - __bfloat162float(hh));
    gWoh[(size_t)n * Dn + k] = hh;
    gWol[(size_t)n * Dn + k] = ll;
}

// ---------------------------------------------------------------------------
// Split-bf16 GEMM via mma.sync.
// mode 0/1: Q/K proj -> gQh/l, gKh/l as bf16 split [b,h,s,d]
// mode 2:   V proj   -> gVth/l as bf16 split TRANSPOSED [b,h,d,s]
// mode 3:   out proj -> fp32 Cout
// ---------------------------------------------------------------------------
#define AS_H 0
#define AS_L (128 * 144)
#define BS_H (2 * 128 * 144)
#define BS_L (2 * 128 * 144 + 64 * 144)
#define SM_BYTES (2 * 128 * 144 + 2 * 64 * 144)   // 55296

__global__ void __launch_bounds__(256)
gemm_tc_kernel(float* __restrict__ Cout, const float* __restrict__ bias, int mode)
{
    extern __shared__ __align__(16) char smem[];
    uint32_t sb = smem_u32(smem);
    int tid  = threadIdx.x;
    int lane = tid & 31;
    int wid  = tid >> 5;
    int wm   = wid & 3;
    int wn   = wid >> 2;

    const __nv_bfloat16 *Ah, *Al, *Bh, *Bl;
    size_t arow, bb;
    if (mode < 3) {
        Ah = gXh; Al = gXl;
        Bh = gWh[mode]; Bl = gWl[mode];
        arow = (size_t)blockIdx.z * Sn + blockIdx.x * 128;
        bb   = (size_t)blockIdx.y * DKn * Dn;
    } else {
        Ah = gOh; Al = gOl;
        Bh = gWoh; Bl = gWol;
        arow = (size_t)blockIdx.x * 128;
        bb   = (size_t)blockIdx.y * 64 * Dn;
    }

    float acc[2][4][4] = {};

    uint32_t aoff = (uint32_t)((wm * 32 + (lane & 15)) * 144 + (lane >> 4) * 16);
    uint32_t boff = (uint32_t)((wn * 32 + (lane & 7) + ((lane >> 4) << 3)) * 144 +
                               (((lane >> 3) & 1) << 4));

    int ldr = tid >> 3;
    int ldcnk = tid & 7;

    for (int ck = 0; ck < 8; ck++) {
        int kof = ck * 64;
        #pragma unroll
        for (int p = 0; p < 4; p++) {
            int r = p * 32 + ldr;
            *(uint4*)(smem + AS_H + r * 144 + ldcnk * 16) =
                *(const uint4*)(Ah + (arow + r) * (size_t)Dn + kof + ldcnk * 8);
            *(uint4*)(smem + AS_L + r * 144 + ldcnk * 16) =
                *(const uint4*)(Al + (arow + r) * (size_t)Dn + kof + ldcnk * 8);
        }
        #pragma unroll
        for (int p = 0; p < 2; p++) {
            int r = p * 32 + ldr;
            *(uint4*)(smem + BS_H + r * 144 + ldcnk * 16) =
                *(const uint4*)(Bh + bb + r * (size_t)Dn + kof + ldcnk * 8);
            *(uint4*)(smem + BS_L + r * 144 + ldcnk * 16) =
                *(const uint4*)(Bl + bb + r * (size_t)Dn + kof + ldcnk * 8);
        }
        __syncthreads();

        #pragma unroll
        for (int kk = 0; kk < 4; kk++) {
            uint32_t ah[2][4], al[2][4], bh[4][2], bl[4][2];
            #pragma unroll
            for (int mf = 0; mf < 2; mf++) {
                ldsm_x4(ah[mf], sb + AS_H + aoff + mf * (16 * 144) + kk * 32);
                ldsm_x4(al[mf], sb + AS_L + aoff + mf * (16 * 144) + kk * 32);
            }
            #pragma unroll
            for (int f2 = 0; f2 < 2; f2++) {
                uint32_t t4[4];
                ldsm_x4(t4, sb + BS_H + boff + f2 * (16 * 144) + kk * 32);
                bh[f2*2+0][0] = t4[0]; bh[f2*2+0][1] = t4[1];
                bh[f2*2+1][0] = t4[2]; bh[f2*2+1][1] = t4[3];
                ldsm_x4(t4, sb + BS_L + boff + f2 * (16 * 144) + kk * 32);
                bl[f2*2+0][0] = t4[0]; bl[f2*2+0][1] = t4[1];
                bl[f2*2+1][0] = t4[2]; bl[f2*2+1][1] = t4[3];
            }
            #pragma unroll
            for (int mf = 0; mf < 2; mf++)
                #pragma unroll
                for (int nf = 0; nf < 4; nf++) {
                    mma16816(acc[mf][nf], ah[mf], bh[nf]);
                    mma16816(acc[mf][nf], ah[mf], bl[nf]);
                    mma16816(acc[mf][nf], al[mf], bh[nf]);
                }
        }
        __syncthreads();
    }

    float bv = bias[0];
    int rbase = wm * 32 + (lane >> 2);
    int cbase = wn * 32 + (lane & 3) * 2;
    int b = blockIdx.z, h = blockIdx.y;

    if (mode == 3) {
        size_t cb = (size_t)blockIdx.x * 128 * Dn + blockIdx.y * 64;
        #pragma unroll
        for (int mf = 0; mf < 2; mf++)
            #pragma unroll
            for (int nf = 0; nf < 4; nf++) {
                int r = rbase + mf * 16, c = cbase + nf * 8;
                *(float2*)(Cout + cb + (size_t)r * Dn + c) =
                    make_float2(acc[mf][nf][0] + bv, acc[mf][nf][1] + bv);
                *(float2*)(Cout + cb + (size_t)(r + 8) * Dn + c) =
                    make_float2(acc[mf][nf][2] + bv, acc[mf][nf][3] + bv);
            }
    } else if (mode < 2) {
        __nv_bfloat16* Ch = (mode == 0) ? gQh : gKh;
        __nv_bfloat16* Cl = (mode == 0) ? gQl : gKl;
        size_t cb = (((size_t)b * Hn + h) * Sn + blockIdx.x * 128) * DKn;
        #pragma unroll
        for (int mf = 0; mf < 2; mf++)
            #pragma unroll
            for (int nf = 0; nf < 4; nf++) {
                int r = rbase + mf * 16, c = cbase + nf * 8;
                uint32_t h0, l0, h1, l1;
                split2(acc[mf][nf][0] + bv, acc[mf][nf][1] + bv, h0, l0);
                split2(acc[mf][nf][2] + bv, acc[mf][nf][3] + bv, h1, l1);
                *(uint32_t*)(Ch + cb + (size_t)r * DKn + c)       = h0;
                *(uint32_t*)(Cl + cb + (size_t)r * DKn + c)       = l0;
                *(uint32_t*)(Ch + cb + (size_t)(r + 8) * DKn + c) = h1;
                *(uint32_t*)(Cl + cb + (size_t)(r + 8) * DKn + c) = l1;
            }
    } else {  // mode 2: V, transposed store [b,h,d,s]
        size_t vb = ((size_t)b * Hn + h) * DKn * Sn;
        int s0 = blockIdx.x * 128;
        #pragma unroll
        for (int mf = 0; mf < 2; mf++)
            #pragma unroll
            for (int nf = 0; nf < 4; nf++) {
                int r = rbase + mf * 16, c = cbase + nf * 8;
                float v0 = acc[mf][nf][0] + bv, v1 = acc[mf][nf][1] + bv;
                float v2 = acc[mf][nf][2] + bv, v3 = acc[mf][nf][3] + bv;
                __nv_bfloat16 h0 = __float2bfloat16(v0), h1 = __float2bfloat16(v1);
                __nv_bfloat16 h2 = __float2bfloat16(v2), h3 = __float2bfloat16(v3);
                gVth[vb + (size_t)(c+0) * Sn + s0 + r]     = h0;
                gVth[vb + (size_t)(c+1) * Sn + s0 + r]     = h1;
                gVth[vb + (size_t)(c+0) * Sn + s0 + r + 8] = h2;
                gVth[vb + (size_t)(c+1) * Sn + s0 + r + 8] = h3;
                gVtl[vb + (size_t)(c+0) * Sn + s0 + r]     = __float2bfloat16(v0 - __bfloat162float(h0));
                gVtl[vb + (size_t)(c+1) * Sn + s0 + r]     = __float2bfloat16(v1 - __bfloat162float(h1));
                gVtl[vb + (size_t)(c+0) * Sn + s0 + r + 8] = __float2bfloat16(v2 - __bfloat162float(h2));
                gVtl[vb + (size_t)(c+1) * Sn + s0 + r + 8] = __float2bfloat16(v3 - __bfloat162float(h3));
            }
    }
}

// ---------------------------------------------------------------------------
// Tensor-core flash attention. 128 queries/CTA, 4 warps x 32 rows.
// Key tiles of 64. Split-bf16 QK^T and P.V; online softmax on fragments.
// ---------------------------------------------------------------------------
#define SQ_H 0
#define SQ_L (128 * 144)
#define SK_H (2 * 128 * 144)
#define SK_L (SK_H + 64 * 144)
#define SV_H (SK_H + 2 * 64 * 144)
#define SV_L (SV_H + 64 * 144)
#define SMSK (SV_H + 2 * 64 * 144)
#define ATT_SM (SMSK + 256)

__global__ void __launch_bounds__(128)
attn_tc_kernel(const int* __restrict__ mask)
{
    extern __shared__ __align__(16) char smem[];
    uint32_t sb = smem_u32(smem);
    int b  = blockIdx.z;
    int h  = blockIdx.y;
    int q0 = blockIdx.x * 128;
    int tid  = threadIdx.x;
    int lane = tid & 31;
    int wid  = tid >> 5;

    size_t qkbase = ((size_t)b * Hn + h) * Sn * DKn;
    size_t vtbase = ((size_t)b * Hn + h) * DKn * Sn;
    const __nv_bfloat16* Qhp = gQh + qkbase + (size_t)q0 * DKn;
    const __nv_bfloat16* Qlp = gQl + qkbase + (size_t)q0 * DKn;
    const __nv_bfloat16* Khp = gKh + qkbase;
    const __nv_bfloat16* Klp = gKl + qkbase;
    const __nv_bfloat16* Vhp = gVth + vtbase;
    const __nv_bfloat16* Vlp = gVtl + vtbase;
    const int* mrow = mask + (size_t)b * Sn;
    int* smask = (int*)(smem + SMSK);

    int ldr = tid >> 3;     // 0..15
    int ldc = tid & 7;      // 16B chunk

    // stage Q tile (128 rows x 64 bf16, hi & lo)
    #pragma unroll
    for (int p = 0; p < 8; p++) {
        int r = p * 16 + ldr;
        *(uint4*)(smem + SQ_H + r * 144 + ldc * 16) =
            *(const uint4*)(Qhp + (size_t)r * DKn + ldc * 8);
        *(uint4*)(smem + SQ_L + r * 144 + ldc * 16) =
            *(const uint4*)(Qlp + (size_t)r * DKn + ldc * 8);
    }

    float oacc[2][8][4] = {};
    float om[2][2] = {{-INFINITY, -INFINITY}, {-INFINITY, -INFINITY}};
    float ol[2][2] = {};

    uint32_t aoffQ = (uint32_t)((wid * 32 + (lane & 15)) * 144 + (lane >> 4) * 16);
    uint32_t boffB = (uint32_t)(((lane & 7) + ((lane >> 4) << 3)) * 144 +
                                (((lane >> 3) & 1) << 4));

    for (int kt = 0; kt < Sn; kt += 64) {
        __syncthreads();
        // stage K (64 rows [t, d]) and Vt (64 rows [d, t]) hi & lo
        #pragma unroll
        for (int p = 0; p < 4; p++) {
            int r = p * 16 + ldr;
            *(uint4*)(smem + SK_H + r * 144 + ldc * 16) =
                *(const uint4*)(Khp + (size_t)(kt + r) * DKn + ldc * 8);
            *(uint4*)(smem + SK_L + r * 144 + ldc * 16) =
                *(const uint4*)(Klp + (size_t)(kt + r) * DKn + ldc * 8);
            *(uint4*)(smem + SV_H + r * 144 + ldc * 16) =
                *(const uint4*)(Vhp + (size_t)r * Sn + kt + ldc * 8);
            *(uint4*)(smem + SV_L + r * 144 + ldc * 16) =
                *(const uint4*)(Vlp + (size_t)r * Sn + kt + ldc * 8);
        }
        if (tid < 64) smask[tid] = mrow[kt + tid];
        __syncthreads();

        // ---- QK^T ----
        float sacc[2][8][4] = {};
        #pragma unroll
        for (int kk = 0; kk < 4; kk++) {
            uint32_t qh[2][4], ql[2][4], kh[8][2], kl[8][2];
            #pragma unroll
            for (int mf = 0; mf < 2; mf++) {
                ldsm_x4(qh[mf], sb + SQ_H + aoffQ + mf * (16 * 144) + kk * 32);
                ldsm_x4(ql[mf], sb + SQ_L + aoffQ + mf * (16 * 144) + kk * 32);
            }
            #pragma unroll
            for (int f2 = 0; f2 < 4; f2++) {
                uint32_t t4[4];
                ldsm_x4(t4, sb + SK_H + boffB + f2 * (16 * 144) + kk * 32);
                kh[f2*2+0][0] = t4[0]; kh[f2*2+0][1] = t4[1];
                kh[f2*2+1][0] = t4[2]; kh[f2*2+1][1] = t4[3];
                ldsm_x4(t4, sb + SK_L + boffB + f2 * (16 * 144) + kk * 32);
                kl[f2*2+0][0] = t4[0]; kl[f2*2+0][1] = t4[1];
                kl[f2*2+1][0] = t4[2]; kl[f2*2+1][1] = t4[3];
            }
            #pragma unroll
            for (int mf = 0; mf < 2; mf++)
                #pragma unroll
                for (int nf = 0; nf < 8; nf++) {
                    mma16816(sacc[mf][nf], qh[mf], kh[nf]);
                    mma16816(sacc[mf][nf], qh[mf], kl[nf]);
                    mma16816(sacc[mf][nf], ql[mf], kh[nf]);
                }
        }

        // ---- masked online softmax on fragments ----
        #pragma unroll
        for (int mf = 0; mf < 2; mf++) {
            float tmax0 = -INFINITY, tmax1 = -INFINITY;
            #pragma unroll
            for (int nf = 0; nf < 8; nf++) {
                int col = nf * 8 + (lane & 3) * 2;
                bool m0 = smask[col] != 0, m1 = smask[col + 1] != 0;
                float* s4 = sacc[mf][nf];
                s4[0] = m0 ? s4[0] * SCALE : NEG_INFV;
                s4[1] = m1 ? s4[1] * SCALE : NEG_INFV;
                s4[2] = m0 ? s4[2] * SCALE : NEG_INFV;
                s4[3] = m1 ? s4[3] * SCALE : NEG_INFV;
                tmax0 = fmaxf(tmax0, fmaxf(s4[0], s4[1]));
                tmax1 = fmaxf(tmax1, fmaxf(s4[2], s4[3]));
            }
            tmax0 = fmaxf(tmax0, __shfl_xor_sync(0xffffffffu, tmax0, 1));
            tmax0 = fmaxf(tmax0, __shfl_xor_sync(0xffffffffu, tmax0, 2));
            tmax1 = fmaxf(tmax1, __shfl_xor_sync(0xffffffffu, tmax1, 1));
            tmax1 = fmaxf(tmax1, __shfl_xor_sync(0xffffffffu, tmax1, 2));

            float newm0 = fmaxf(om[mf][0], tmax0);
            float newm1 = fmaxf(om[mf][1], tmax1);
            float corr0 = __expf(om[mf][0] - newm0);
            float corr1 = __expf(om[mf][1] - newm1);
            om[mf][0] = newm0; om[mf][1] = newm1;

            float ls0 = 0.f, ls1 = 0.f;
            #pragma unroll
            for (int nf = 0; nf < 8; nf++) {
                float* s4 = sacc[mf][nf];
                s4[0] = __expf(s4[0] - newm0); ls0 += s4[0];
                s4[1] = __expf(s4[1] - newm0); ls0 += s4[1];
                s4[2] = __expf(s4[2] - newm1); ls1 += s4[2];
                s4[3] = __expf(s4[3] - newm1); ls1 += s4[3];
            }
            ls0 += __shfl_xor_sync(0xffffffffu, ls0, 1);
            ls0 += __shfl_xor_sync(0xffffffffu, ls0, 2);
            ls1 += __shfl_xor_sync(0xffffffffu, ls1, 1);
            ls1 += __shfl_xor_sync(0xffffffffu, ls1, 2);
            ol[mf][0] = ol[mf][0] * corr0 + ls0;
            ol[mf][1] = ol[mf][1] * corr1 + ls1;

            #pragma unroll
            for (int nf = 0; nf < 8; nf++) {
                oacc[mf][nf][0] *= corr0;
                oacc[mf][nf][1] *= corr0;
                oacc[mf][nf][2] *= corr1;
                oacc[mf][nf][3] *= corr1;
            }
        }

        // ---- P . V ----
        #pragma unroll
        for (int kk = 0; kk < 4; kk++) {
            uint32_t ph[2][4], pl2[2][4], vh[8][2], vl[8][2];
            #pragma unroll
            for (int mf = 0; mf < 2; mf++) {
                float* pA = sacc[mf][2*kk];
                float* pB = sacc[mf][2*kk + 1];
                split2(pA[0], pA[1], ph[mf][0], pl2[mf][0]);
                split2(pA[2], pA[3], ph[mf][1], pl2[mf][1]);
                split2(pB[0], pB[1], ph[mf][2], pl2[mf][2]);
                split2(pB[2], pB[3], ph[mf][3], pl2[mf][3]);
            }
            #pragma unroll
            for (int f2 = 0; f2 < 4; f2++) {
                uint32_t t4[4];
                ldsm_x4(t4, sb + SV_H + boffB + f2 * (16 * 144) + kk * 32);
                vh[f2*2+0][0] = t4[0]; vh[f2*2+0][1] = t4[1];
                vh[f2*2+1][0] = t4[2]; vh[f2*2+1][1] = t4[3];
                ldsm_x4(t4, sb + SV_L + boffB + f2 * (16 * 144) + kk * 32);
                vl[f2*2+0][0] = t4[0]; vl[f2*2+0][1] = t4[1];
                vl[f2*2+1][0] = t4[2]; vl[f2*2+1][1] = t4[3];
            }
            #pragma unroll
            for (int mf = 0; mf < 2; mf++)
                #pragma unroll
                for (int nf = 0; nf < 8; nf++) {
                    mma16816(oacc[mf][nf], ph[mf], vh[nf]);
                    mma16816(oacc[mf][nf], ph[mf], vl[nf]);
                    mma16816(oacc[mf][nf], pl2[mf], vh[nf]);
                }
        }
    }

    // ---- epilogue: normalize, split to bf16 hi/lo, write gOh/gOl ----
    size_t ob = ((size_t)b * Sn + q0) * Dn + h * DKn;
    #pragma unroll
    for (int mf = 0; mf < 2; mf++) {
        float i0 = 1.0f / ol[mf][0];
        float i1 = 1.0f / ol[mf][1];
        #pragma unroll
        for (int nf = 0; nf < 8; nf++) {
            int r = wid * 32 + (lane >> 2) + mf * 16;
            int c = nf * 8 + (lane & 3) * 2;
            uint32_t h0, l0, h1, l1;
            split2(oacc[mf][nf][0] * i0, oacc[mf][nf][1] * i0, h0, l0);
            split2(oacc[mf][nf][2] * i1, oacc[mf][nf][3] * i1, h1, l1);
            *(uint32_t*)(gOh + ob + (size_t)r * Dn + c)       = h0;
            *(uint32_t*)(gOl + ob + (size_t)r * Dn + c)       = l0;
            *(uint32_t*)(gOh + ob + (size_t)(r + 8) * Dn + c) = h1;
            *(uint32_t*)(gOl + ob + (size_t)(r + 8) * Dn + c) = l1;
        }
    }
}

// ---------------------------------------------------------------------------
extern "C" void kernel_launch(void* const* d_in, const int* in_sizes, int n_in,
                              void* d_out, int out_size)
{
    const float* x    = (const float*)d_in[0];
    const int*   mask = (const int*)  d_in[1];
    const float* Wq   = (const float*)d_in[2];
    const float* Wk   = (const float*)d_in[3];
    const float* Wv   = (const float*)d_in[4];
    const float* Wo   = (const float*)d_in[5];
    const float* bias = (const float*)d_in[6];
    float* out = (float*)d_out;

    cudaFuncSetAttribute(gemm_tc_kernel,
                         cudaFuncAttributeMaxDynamicSharedMemorySize, SM_BYTES);
    cudaFuncSetAttribute(attn_tc_kernel,
                         cudaFuncAttributeMaxDynamicSharedMemorySize, ATT_SM);

    cvt_kernel<<<(Bn * Sn * Dn) / (4 * 256), 256>>>(x);
    dim3 gw(128, 1, Hn);
    wprep_kernel<<<gw, 256>>>(Wq, 0);
    wprep_kernel<<<gw, 256>>>(Wk, 1);
    wprep_kernel<<<gw, 256>>>(Wv, 2);
    woprep_kernel<<<1024, 256>>>(Wo);

    dim3 gq(Sn / 128, Hn, Bn);
    gemm_tc_kernel<<<gq, 256, SM_BYTES>>>(nullptr, bias, 0);
    gemm_tc_kernel<<<gq, 256, SM_BYTES>>>(nullptr, bias, 1);
    gemm_tc_kernel<<<gq, 256, SM_BYTES>>>(nullptr, bias, 2);

    dim3 ga(Sn / 128, Hn, Bn);
    attn_tc_kernel<<<ga, 128, ATT_SM>>>(mask);

    dim3 gp((Bn * Sn) / 128, Dn / 64, 1);
    gemm_tc_kernel<<<gp, 256, SM_BYTES>>>(out, bias, 3);
}

// round 5
// speedup vs baseline: 3.8639x; 1.0043x over previous
#include <cuda_runtime.h>
#include <cuda_bf16.h>
#include <math.h>
#include <stdint.h>

#define Bn 32
#define Sn 512
#define Dn 512
#define Hn 8
#define DKn 64
#define NEG_INFV -1e30f
#define SCALE 0.125f

// ---------------------------------------------------------------------------
// Scratch (__device__ globals)
// ---------------------------------------------------------------------------
__device__ __align__(16) __nv_bfloat16 gXh[(size_t)Bn*Sn*Dn];
__device__ __align__(16) __nv_bfloat16 gXl[(size_t)Bn*Sn*Dn];
__device__ __align__(16) __nv_bfloat16 gOh[(size_t)Bn*Sn*Dn];
__device__ __align__(16) __nv_bfloat16 gOl[(size_t)Bn*Sn*Dn];
__device__ __align__(16) __nv_bfloat16 gWh[3][(size_t)Hn*DKn*Dn];
__device__ __align__(16) __nv_bfloat16 gWl[3][(size_t)Hn*DKn*Dn];
__device__ __align__(16) __nv_bfloat16 gWoh[(size_t)Dn*Dn];
__device__ __align__(16) __nv_bfloat16 gWol[(size_t)Dn*Dn];
__device__ __align__(16) __nv_bfloat16 gQh[(size_t)Bn*Hn*Sn*DKn];
__device__ __align__(16) __nv_bfloat16 gQl[(size_t)Bn*Hn*Sn*DKn];
__device__ __align__(16) __nv_bfloat16 gKh[(size_t)Bn*Hn*Sn*DKn];
__device__ __align__(16) __nv_bfloat16 gKl[(size_t)Bn*Hn*Sn*DKn];
__device__ __align__(16) __nv_bfloat16 gVth[(size_t)Bn*Hn*DKn*Sn];
__device__ __align__(16) __nv_bfloat16 gVtl[(size_t)Bn*Hn*DKn*Sn];

// ---------------------------------------------------------------------------
// helpers
// ---------------------------------------------------------------------------
__device__ __forceinline__ uint32_t smem_u32(const void* p) {
    uint32_t a;
    asm("{ .reg .u64 t; cvta.to.shared.u64 t, %1; cvt.u32.u64 %0, t; }" : "=r"(a) : "l"(p));
    return a;
}

__device__ __forceinline__ void ldsm_x4(uint32_t* r, uint32_t addr) {
    asm volatile("ldmatrix.sync.aligned.m8n8.x4.shared.b16 {%0,%1,%2,%3}, [%4];"
        : "=r"(r[0]), "=r"(r[1]), "=r"(r[2]), "=r"(r[3]) : "r"(addr));
}

__device__ __forceinline__ void mma16816(float* d, const uint32_t* a, const uint32_t* b) {
    asm volatile("mma.sync.aligned.m16n8k16.row.col.f32.bf16.bf16.f32 "
        "{%0,%1,%2,%3}, {%4,%5,%6,%7}, {%8,%9}, {%0,%1,%2,%3};"
        : "+f"(d[0]), "+f"(d[1]), "+f"(d[2]), "+f"(d[3])
        : "r"(a[0]), "r"(a[1]), "r"(a[2]), "r"(a[3]), "r"(b[0]), "r"(b[1]));
}

__device__ __forceinline__ void split2(float a, float b, uint32_t& hi, uint32_t& lo) {
    __nv_bfloat16 ha = __float2bfloat16(a), hb = __float2bfloat16(b);
    __nv_bfloat16 la = __float2bfloat16(a - __bfloat162float(ha));
    __nv_bfloat16 lb = __float2bfloat16(b - __bfloat162float(hb));
    __nv_bfloat162 H(ha, hb), L(la, lb);
    hi = *(uint32_t*)&H; lo = *(uint32_t*)&L;
}

#define CP16(dst, src) asm volatile("cp.async.cg.shared.global [%0], [%1], 16;" :: "r"(dst), "l"(src))
#define CP_COMMIT()    asm volatile("cp.async.commit_group;")
#define CP_WAIT(n)     asm volatile("cp.async.wait_group %0;" :: "n"(n))

// ---------------------------------------------------------------------------
// Prep kernels
// ---------------------------------------------------------------------------
__global__ void cvt_kernel(const float* __restrict__ xin)
{
    size_t i = ((size_t)blockIdx.x * blockDim.x + threadIdx.x) * 4;
    float4 v = *(const float4*)(xin + i);
    uint32_t h0, l0, h1, l1;
    split2(v.x, v.y, h0, l0);
    split2(v.z, v.w, h1, l1);
    uint32_t* hp = (uint32_t*)(gXh + i);
    uint32_t* lp = (uint32_t*)(gXl + i);
    hp[0] = h0; hp[1] = h1;
    lp[0] = l0; lp[1] = l1;
}

__global__ void wprep_all(const float* __restrict__ Wq,
                          const float* __restrict__ Wk,
                          const float* __restrict__ Wv)
{
    int z = blockIdx.z;
    int which = z >> 3;
    int h = z & 7;
    const float* W = (which == 0) ? Wq : (which == 1) ? Wk : Wv;
    int idx = blockIdx.x * 256 + threadIdx.x;
    int n = idx >> 9, k = idx & 511;
    float a = W[(size_t)h * Dn * DKn + (size_t)k * DKn + n];
    __nv_bfloat16 hh = __float2bfloat16(a);
    __nv_bfloat16 ll = __float2bfloat16(a - __bfloat162float(hh));
    size_t o = (size_t)h * DKn * Dn + (size_t)n * Dn + k;
    gWh[which][o] = hh;
    gWl[which][o] = ll;
}

__global__ void woprep_kernel(const float* __restrict__ Wo)
{
    int idx = blockIdx.x * 256 + threadIdx.x;
    int n = idx >> 9, k = idx & 511;
    float a = Wo[(size_t)k * Dn + n];
    __nv_bfloat16 hh = __float2bfloat16(a);
    __nv_bfloat16 ll = __float2bfloat16(a - __bfloat162float(hh));
    gWoh[(size_t)n * Dn + k] = hh;
    gWol[(size_t)n * Dn + k] = ll;
}

// ---------------------------------------------------------------------------
// Split-bf16 GEMM via mma.sync with cp.async double buffering.
// mode 0/1: Q/K proj -> split bf16 [b,h,s,d]; mode 2: V -> split bf16 [b,h,d,s]
// mode 3: out proj -> fp32 Cout
// ---------------------------------------------------------------------------
#define AS_H 0
#define AS_L 18432
#define BS_H 36864
#define BS_L 46080
#define CHUNK_B 55296
#define SM_BYTES (2 * CHUNK_B)    // 110592

__global__ void __launch_bounds__(256)
gemm_tc_kernel(float* __restrict__ Cout, const float* __restrict__ bias, int mode)
{
    extern __shared__ __align__(16) char smem[];
    uint32_t sb = smem_u32(smem);
    int tid  = threadIdx.x;
    int lane = tid & 31;
    int wid  = tid >> 5;
    int wm   = wid & 3;
    int wn   = wid >> 2;

    const __nv_bfloat16 *Ah, *Al, *Bh, *Bl;
    size_t arow, bb;
    if (mode < 3) {
        Ah = gXh; Al = gXl;
        Bh = gWh[mode]; Bl = gWl[mode];
        arow = (size_t)blockIdx.z * Sn + blockIdx.x * 128;
        bb   = (size_t)blockIdx.y * DKn * Dn;
    } else {
        Ah = gOh; Al = gOl;
        Bh = gWoh; Bl = gWol;
        arow = (size_t)blockIdx.x * 128;
        bb   = (size_t)blockIdx.y * 64 * Dn;
    }

    float acc[2][4][4] = {};

    uint32_t aoff = (uint32_t)((wm * 32 + (lane & 15)) * 144 + (lane >> 4) * 16);
    uint32_t boff = (uint32_t)((wn * 32 + (lane & 7) + ((lane >> 4) << 3)) * 144 +
                               (((lane >> 3) & 1) << 4));

    int ldr = tid >> 3;      // 0..31
    int ldcnk = tid & 7;

    // issue one chunk's cp.asyncs into buffer `bo`
    auto issue = [&](int ck, uint32_t bo) {
        int kof = ck * 64;
        #pragma unroll
        for (int p = 0; p < 4; p++) {
            int r = p * 32 + ldr;
            uint32_t d = sb + bo + r * 144 + ldcnk * 16;
            CP16(d + AS_H, Ah + (arow + r) * (size_t)Dn + kof + ldcnk * 8);
            CP16(d + AS_L, Al + (arow + r) * (size_t)Dn + kof + ldcnk * 8);
        }
        #pragma unroll
        for (int p = 0; p < 2; p++) {
            int r = p * 32 + ldr;
            uint32_t d = sb + bo + r * 144 + ldcnk * 16;
            CP16(d + BS_H, Bh + bb + r * (size_t)Dn + kof + ldcnk * 8);
            CP16(d + BS_L, Bl + bb + r * (size_t)Dn + kof + ldcnk * 8);
        }
    };

    issue(0, 0);
    CP_COMMIT();

    for (int ck = 0; ck < 8; ck++) {
        uint32_t bo = (uint32_t)(ck & 1) * CHUNK_B;
        if (ck < 7) {
            issue(ck + 1, (uint32_t)((ck + 1) & 1) * CHUNK_B);
            CP_COMMIT();
            CP_WAIT(1);
        } else {
            CP_WAIT(0);
        }
        __syncthreads();

        #pragma unroll
        for (int kk = 0; kk < 4; kk++) {
            uint32_t ah[2][4], al[2][4], bh[4][2], bl[4][2];
            #pragma unroll
            for (int mf = 0; mf < 2; mf++) {
                ldsm_x4(ah[mf], sb + bo + AS_H + aoff + mf * (16 * 144) + kk * 32);
                ldsm_x4(al[mf], sb + bo + AS_L + aoff + mf * (16 * 144) + kk * 32);
            }
            #pragma unroll
            for (int f2 = 0; f2 < 2; f2++) {
                uint32_t t4[4];
                ldsm_x4(t4, sb + bo + BS_H + boff + f2 * (16 * 144) + kk * 32);
                bh[f2*2+0][0] = t4[0]; bh[f2*2+0][1] = t4[1];
                bh[f2*2+1][0] = t4[2]; bh[f2*2+1][1] = t4[3];
                ldsm_x4(t4, sb + bo + BS_L + boff + f2 * (16 * 144) + kk * 32);
                bl[f2*2+0][0] = t4[0]; bl[f2*2+0][1] = t4[1];
                bl[f2*2+1][0] = t4[2]; bl[f2*2+1][1] = t4[3];
            }
            #pragma unroll
            for (int mf = 0; mf < 2; mf++)
                #pragma unroll
                for (int nf = 0; nf < 4; nf++) {
                    mma16816(acc[mf][nf], ah[mf], bh[nf]);
                    mma16816(acc[mf][nf], ah[mf], bl[nf]);
                    mma16816(acc[mf][nf], al[mf], bh[nf]);
                }
        }
        __syncthreads();
    }

    float bv = bias[0];
    int rbase = wm * 32 + (lane >> 2);
    int cbase = wn * 32 + (lane & 3) * 2;
    int b = blockIdx.z, h = blockIdx.y;

    if (mode == 3) {
        size_t cb = (size_t)blockIdx.x * 128 * Dn + blockIdx.y * 64;
        #pragma unroll
        for (int mf = 0; mf < 2; mf++)
            #pragma unroll
            for (int nf = 0; nf < 4; nf++) {
                int r = rbase + mf * 16, c = cbase + nf * 8;
                *(float2*)(Cout + cb + (size_t)r * Dn + c) =
                    make_float2(acc[mf][nf][0] + bv, acc[mf][nf][1] + bv);
                *(float2*)(Cout + cb + (size_t)(r + 8) * Dn + c) =
                    make_float2(acc[mf][nf][2] + bv, acc[mf][nf][3] + bv);
            }
    } else if (mode < 2) {
        __nv_bfloat16* Ch = (mode == 0) ? gQh : gKh;
        __nv_bfloat16* Cl = (mode == 0) ? gQl : gKl;
        size_t cb = (((size_t)b * Hn + h) * Sn + blockIdx.x * 128) * DKn;
        #pragma unroll
        for (int mf = 0; mf < 2; mf++)
            #pragma unroll
            for (int nf = 0; nf < 4; nf++) {
                int r = rbase + mf * 16, c = cbase + nf * 8;
                uint32_t h0, l0, h1, l1;
                split2(acc[mf][nf][0] + bv, acc[mf][nf][1] + bv, h0, l0);
                split2(acc[mf][nf][2] + bv, acc[mf][nf][3] + bv, h1, l1);
                *(uint32_t*)(Ch + cb + (size_t)r * DKn + c)       = h0;
                *(uint32_t*)(Cl + cb + (size_t)r * DKn + c)       = l0;
                *(uint32_t*)(Ch + cb + (size_t)(r + 8) * DKn + c) = h1;
                *(uint32_t*)(Cl + cb + (size_t)(r + 8) * DKn + c) = l1;
            }
    } else {
        size_t vb = ((size_t)b * Hn + h) * DKn * Sn;
        int s0 = blockIdx.x * 128;
        #pragma unroll
        for (int mf = 0; mf < 2; mf++)
            #pragma unroll
            for (int nf = 0; nf < 4; nf++) {
                int r = rbase + mf * 16, c = cbase + nf * 8;
                float v0 = acc[mf][nf][0] + bv, v1 = acc[mf][nf][1] + bv;
                float v2 = acc[mf][nf][2] + bv, v3 = acc[mf][nf][3] + bv;
                __nv_bfloat16 h0 = __float2bfloat16(v0), h1 = __float2bfloat16(v1);
                __nv_bfloat16 h2 = __float2bfloat16(v2), h3 = __float2bfloat16(v3);
                gVth[vb + (size_t)(c+0) * Sn + s0 + r]     = h0;
                gVth[vb + (size_t)(c+1) * Sn + s0 + r]     = h1;
                gVth[vb + (size_t)(c+0) * Sn + s0 + r + 8] = h2;
                gVth[vb + (size_t)(c+1) * Sn + s0 + r + 8] = h3;
                gVtl[vb + (size_t)(c+0) * Sn + s0 + r]     = __float2bfloat16(v0 - __bfloat162float(h0));
                gVtl[vb + (size_t)(c+1) * Sn + s0 + r]     = __float2bfloat16(v1 - __bfloat162float(h1));
                gVtl[vb + (size_t)(c+0) * Sn + s0 + r + 8] = __float2bfloat16(v2 - __bfloat162float(h2));
                gVtl[vb + (size_t)(c+1) * Sn + s0 + r + 8] = __float2bfloat16(v3 - __bfloat162float(h3));
            }
    }
}

// ---------------------------------------------------------------------------
// Tensor-core flash attention. 128 queries/CTA, 256 threads, 8 warps x 16 rows.
// ---------------------------------------------------------------------------
#define SQ_H 0
#define SQ_L (128 * 144)
#define SK_H (2 * 128 * 144)
#define SK_L (SK_H + 64 * 144)
#define SV_H (SK_H + 2 * 64 * 144)
#define SV_L (SV_H + 64 * 144)
#define SMSK (SV_H + 2 * 64 * 144)
#define ATT_SM (SMSK + 256)

__global__ void __launch_bounds__(256)
attn_tc_kernel(const int* __restrict__ mask)
{
    extern __shared__ __align__(16) char smem[];
    uint32_t sb = smem_u32(smem);
    int b  = blockIdx.z;
    int h  = blockIdx.y;
    int q0 = blockIdx.x * 128;
    int tid  = threadIdx.x;
    int lane = tid & 31;
    int wid  = tid >> 5;

    size_t qkbase = ((size_t)b * Hn + h) * Sn * DKn;
    size_t vtbase = ((size_t)b * Hn + h) * DKn * Sn;
    const __nv_bfloat16* Qhp = gQh + qkbase + (size_t)q0 * DKn;
    const __nv_bfloat16* Qlp = gQl + qkbase + (size_t)q0 * DKn;
    const __nv_bfloat16* Khp = gKh + qkbase;
    const __nv_bfloat16* Klp = gKl + qkbase;
    const __nv_bfloat16* Vhp = gVth + vtbase;
    const __nv_bfloat16* Vlp = gVtl + vtbase;
    const int* mrow = mask + (size_t)b * Sn;
    int* smask = (int*)(smem + SMSK);

    int ldr = tid >> 3;     // 0..31
    int ldc = tid & 7;

    // stage Q tile (128 x 64, hi & lo) via cp.async
    #pragma unroll
    for (int p = 0; p < 4; p++) {
        int r = p * 32 + ldr;
        uint32_t d = sb + r * 144 + ldc * 16;
        CP16(d + SQ_H, Qhp + (size_t)r * DKn + ldc * 8);
        CP16(d + SQ_L, Qlp + (size_t)r * DKn + ldc * 8);
    }
    CP_COMMIT();

    float oacc[8][4] = {};
    float om0 = -INFINITY, om1 = -INFINITY;
    float ol0 = 0.f, ol1 = 0.f;

    uint32_t aoffQ = (uint32_t)((wid * 16 + (lane & 15)) * 144 + (lane >> 4) * 16);
    uint32_t boffB = (uint32_t)(((lane & 7) + ((lane >> 4) << 3)) * 144 +
                                (((lane >> 3) & 1) << 4));

    for (int kt = 0; kt < Sn; kt += 64) {
        __syncthreads();    // prior tile's mma done; K/V smem reusable
        #pragma unroll
        for (int p = 0; p < 2; p++) {
            int r = p * 32 + ldr;
            uint32_t d = sb + r * 144 + ldc * 16;
            CP16(d + SK_H, Khp + (size_t)(kt + r) * DKn + ldc * 8);
            CP16(d + SK_L, Klp + (size_t)(kt + r) * DKn + ldc * 8);
            CP16(d + SV_H, Vhp + (size_t)r * Sn + kt + ldc * 8);
            CP16(d + SV_L, Vlp + (size_t)r * Sn + kt + ldc * 8);
        }
        CP_COMMIT();
        if (tid < 64) smask[tid] = mrow[kt + tid];
        CP_WAIT(0);
        __syncthreads();

        // ---- QK^T ----
        float sacc[8][4] = {};
        #pragma unroll
        for (int kk = 0; kk < 4; kk++) {
            uint32_t qh[4], ql[4], kh[8][2], kl[8][2];
            ldsm_x4(qh, sb + SQ_H + aoffQ + kk * 32);
            ldsm_x4(ql, sb + SQ_L + aoffQ + kk * 32);
            #pragma unroll
            for (int f2 = 0; f2 < 4; f2++) {
                uint32_t t4[4];
                ldsm_x4(t4, sb + SK_H + boffB + f2 * (16 * 144) + kk * 32);
                kh[f2*2+0][0] = t4[0]; kh[f2*2+0][1] = t4[1];
                kh[f2*2+1][0] = t4[2]; kh[f2*2+1][1] = t4[3];
                ldsm_x4(t4, sb + SK_L + boffB + f2 * (16 * 144) + kk * 32);
                kl[f2*2+0][0] = t4[0]; kl[f2*2+0][1] = t4[1];
                kl[f2*2+1][0] = t4[2]; kl[f2*2+1][1] = t4[3];
            }
            #pragma unroll
            for (int nf = 0; nf < 8; nf++) {
                mma16816(sacc[nf], qh, kh[nf]);
                mma16816(sacc[nf], qh, kl[nf]);
                mma16816(sacc[nf], ql, kh[nf]);
            }
        }

        // ---- masked online softmax ----
        {
            float tmax0 = -INFINITY, tmax1 = -INFINITY;
            #pragma unroll
            for (int nf = 0; nf < 8; nf++) {
                int col = nf * 8 + (lane & 3) * 2;
                bool m0 = smask[col] != 0, m1 = smask[col + 1] != 0;
                float* s4 = sacc[nf];
                s4[0] = m0 ? s4[0] * SCALE : NEG_INFV;
                s4[1] = m1 ? s4[1] * SCALE : NEG_INFV;
                s4[2] = m0 ? s4[2] * SCALE : NEG_INFV;
                s4[3] = m1 ? s4[3] * SCALE : NEG_INFV;
                tmax0 = fmaxf(tmax0, fmaxf(s4[0], s4[1]));
                tmax1 = fmaxf(tmax1, fmaxf(s4[2], s4[3]));
            }
            tmax0 = fmaxf(tmax0, __shfl_xor_sync(0xffffffffu, tmax0, 1));
            tmax0 = fmaxf(tmax0, __shfl_xor_sync(0xffffffffu, tmax0, 2));
            tmax1 = fmaxf(tmax1, __shfl_xor_sync(0xffffffffu, tmax1, 1));
            tmax1 = fmaxf(tmax1, __shfl_xor_sync(0xffffffffu, tmax1, 2));

            float newm0 = fmaxf(om0, tmax0);
            float newm1 = fmaxf(om1, tmax1);
            float corr0 = __expf(om0 - newm0);
            float corr1 = __expf(om1 - newm1);
            om0 = newm0; om1 = newm1;

            float ls0 = 0.f, ls1 = 0.f;
            #pragma unroll
            for (int nf = 0; nf < 8; nf++) {
                float* s4 = sacc[nf];
                s4[0] = __expf(s4[0] - newm0); ls0 += s4[0];
                s4[1] = __expf(s4[1] - newm0); ls0 += s4[1];
                s4[2] = __expf(s4[2] - newm1); ls1 += s4[2];
                s4[3] = __expf(s4[3] - newm1); ls1 += s4[3];
            }
            ls0 += __shfl_xor_sync(0xffffffffu, ls0, 1);
            ls0 += __shfl_xor_sync(0xffffffffu, ls0, 2);
            ls1 += __shfl_xor_sync(0xffffffffu, ls1, 1);
            ls1 += __shfl_xor_sync(0xffffffffu, ls1, 2);
            ol0 = ol0 * corr0 + ls0;
            ol1 = ol1 * corr1 + ls1;

            #pragma unroll
            for (int nf = 0; nf < 8; nf++) {
                oacc[nf][0] *= corr0;
                oacc[nf][1] *= corr0;
                oacc[nf][2] *= corr1;
                oacc[nf][3] *= corr1;
            }
        }

        // ---- P . V ----
        #pragma unroll
        for (int kk = 0; kk < 4; kk++) {
            uint32_t ph[4], pl2[4], vh[8][2], vl[8][2];
            float* pA = sacc[2*kk];
            float* pB = sacc[2*kk + 1];
            split2(pA[0], pA[1], ph[0], pl2[0]);
            split2(pA[2], pA[3], ph[1], pl2[1]);
            split2(pB[0], pB[1], ph[2], pl2[2]);
            split2(pB[2], pB[3], ph[3], pl2[3]);
            #pragma unroll
            for (int f2 = 0; f2 < 4; f2++) {
                uint32_t t4[4];
                ldsm_x4(t4, sb + SV_H + boffB + f2 * (16 * 144) + kk * 32);
                vh[f2*2+0][0] = t4[0]; vh[f2*2+0][1] = t4[1];
                vh[f2*2+1][0] = t4[2]; vh[f2*2+1][1] = t4[3];
                ldsm_x4(t4, sb + SV_L + boffB + f2 * (16 * 144) + kk * 32);
                vl[f2*2+0][0] = t4[0]; vl[f2*2+0][1] = t4[1];
                vl[f2*2+1][0] = t4[2]; vl[f2*2+1][1] = t4[3];
            }
            #pragma unroll
            for (int nf = 0; nf < 8; nf++) {
                mma16816(oacc[nf], ph, vh[nf]);
                mma16816(oacc[nf], ph, vl[nf]);
                mma16816(oacc[nf], pl2, vh[nf]);
            }
        }
    }

    // ---- epilogue: normalize, split bf16 hi/lo, write gOh/gOl ----
    size_t ob = ((size_t)b * Sn + q0) * Dn + h * DKn;
    float i0 = 1.0f / ol0;
    float i1 = 1.0f / ol1;
    int r = wid * 16 + (lane >> 2);
    #pragma unroll
    for (int nf = 0; nf < 8; nf++) {
        int c = nf * 8 + (lane & 3) * 2;
        uint32_t h0, l0, h1, l1;
        split2(oacc[nf][0] * i0, oacc[nf][1] * i0, h0, l0);
        split2(oacc[nf][2] * i1, oacc[nf][3] * i1, h1, l1);
        *(uint32_t*)(gOh + ob + (size_t)r * Dn + c)       = h0;
        *(uint32_t*)(gOl + ob + (size_t)r * Dn + c)       = l0;
        *(uint32_t*)(gOh + ob + (size_t)(r + 8) * Dn + c) = h1;
        *(uint32_t*)(gOl + ob + (size_t)(r + 8) * Dn + c) = l1;
    }
}

// ---------------------------------------------------------------------------
extern "C" void kernel_launch(void* const* d_in, const int* in_sizes, int n_in,
                              void* d_out, int out_size)
{
    const float* x    = (const float*)d_in[0];
    const int*   mask = (const int*)  d_in[1];
    const float* Wq   = (const float*)d_in[2];
    const float* Wk   = (const float*)d_in[3];
    const float* Wv   = (const float*)d_in[4];
    const float* Wo   = (const float*)d_in[5];
    const float* bias = (const float*)d_in[6];
    float* out = (float*)d_out;

    cudaFuncSetAttribute(gemm_tc_kernel,
                         cudaFuncAttributeMaxDynamicSharedMemorySize, SM_BYTES);
    cudaFuncSetAttribute(attn_tc_kernel,
                         cudaFuncAttributeMaxDynamicSharedMemorySize, ATT_SM);

    cvt_kernel<<<(Bn * Sn * Dn) / (4 * 256), 256>>>(x);
    dim3 gw(128, 1, 24);
    wprep_all<<<gw, 256>>>(Wq, Wk, Wv);
    woprep_kernel<<<1024, 256>>>(Wo);

    dim3 gq(Sn / 128, Hn, Bn);
    gemm_tc_kernel<<<gq, 256, SM_BYTES>>>(nullptr, bias, 0);
    gemm_tc_kernel<<<gq, 256, SM_BYTES>>>(nullptr, bias, 1);
    gemm_tc_kernel<<<gq, 256, SM_BYTES>>>(nullptr, bias, 2);

    dim3 ga(Sn / 128, Hn, Bn);
    attn_tc_kernel<<<ga, 256, ATT_SM>>>(mask);

    dim3 gp((Bn * Sn) / 128, Dn / 64, 1);
    gemm_tc_kernel<<<gp, 256, SM_BYTES>>>(out, bias, 3);
}